// round 8
// baseline (speedup 1.0000x reference)
#include <cuda_runtime.h>
#include <mma.h>
#include <cstdint>

using namespace nvcuda;

#define B_   256
#define K_   256
#define C_   128
#define KG_  64
#define OUTC 117
#define OCH  183

// scratch (allocation-free rule: __device__ globals)
__device__ float g_net1[B_ * C_ * K_];   // pre-BN layer1 output (B,128,256)
__device__ float g_net2[B_ * C_ * K_];   // pre-BN layer2 output
__device__ float g_t[B_ * OUTC * K_];    // layer3 output (B,117,256)
__device__ float g_s[2][C_];             // BN sum accumulators
__device__ float g_s2[2][C_];            // BN sum-of-squares accumulators
__device__ float g_a[2][C_], g_d[2][C_]; // folded BN scale/shift

// ===========================================================================
// prep: objectness_label + get_index + zero BN accumulators (fused)
// ===========================================================================
__global__ void prep_kernel(const float* __restrict__ xyz,
                            const float* __restrict__ gt,
                            const int* __restrict__ pred,
                            float* __restrict__ lbl,
                            float* __restrict__ idxo,
                            float* __restrict__ sum1) {
    int b = blockIdx.x, k = threadIdx.x;
    if (b == 0 && k < C_) {
        g_s[0][k] = 0.f; g_s[1][k] = 0.f;
        g_s2[0][k] = 0.f; g_s2[1][k] = 0.f;
    }
    __shared__ float sg[KG_ * 3];
    if (k < KG_ * 3) sg[k] = gt[b * KG_ * 3 + k];
    __syncthreads();
    const float* p = xyz + (b * K_ + k) * 3;
    float x = p[0], y = p[1], z = p[2];
    float mn = 1e30f;
#pragma unroll 8
    for (int g = 0; g < KG_; g++) {
        float dx = x - sg[g * 3 + 0];
        float dy = y - sg[g * 3 + 1];
        float dz = z - sg[g * 3 + 2];
        mn = fminf(mn, dx * dx + dy * dy + dz * dz);
    }
    lbl[b * K_ + k] = (sqrtf(mn + 1e-6f) < 0.3f) ? 1.0f : 0.0f;

    int pv = pred[b * K_ + k];
    __shared__ int sc[K_];
    __shared__ int res[K_];
    sc[k] = pv;
    res[k] = k;
    __syncthreads();
    for (int off = 1; off < K_; off <<= 1) {
        int add = (k >= off) ? sc[k - off] : 0;
        __syncthreads();
        sc[k] += add;
        __syncthreads();
    }
    int num = sc[K_ - 1];
    int excl = sc[k] - pv;
    if (pv == 1) res[excl] = k;
    __syncthreads();
    idxo[b * K_ + k] = (float)((k < num) ? res[k] : k);
    if (k == 0) sum1[b] = (float)num;
}

// ===========================================================================
// wmma tf32 GEMM: Y[b,m,n] = sum_c W[m,c] * X[b,c,n] + bias[m]
// grid = (2 n-halves, B_), 256 threads (8 warps), CTA tile 128x128,
// warp tile 32x64 (2x4 frags of 16x16), K chunked by 32.
// MODE 0: X = concat(X0,X1) along c.  MODE 1: X = relu(X0*a[c]+d[c]).
// STATS : fused per-channel sum/sum^2 via shfl + atomics.
// ===========================================================================
#define ALD 40     // As leading dim (floats)
#define BLD 132    // Bs leading dim
#define DLD 68     // Dsm leading dim

template <int CIN, int MODE, int STATS>
__global__ void __launch_bounds__(256)
wmma_gemm(const float* __restrict__ W, const float* __restrict__ bias,
          const float* __restrict__ X0, const float* __restrict__ X1,
          const float* __restrict__ aa, const float* __restrict__ dd,
          float* __restrict__ Y, int M,
          float* __restrict__ sS, float* __restrict__ sS2) {
    __shared__ float smbuf[C_ * ALD + 32 * BLD];   // 9344 floats (37.4 KB)
    float* As = smbuf;                 // [128][ALD]
    float* Bs = smbuf + C_ * ALD;      // [32][BLD]
    float* Dsm = smbuf;                // reused post-mainloop [128][DLD]

    int tid = threadIdx.x;
    int w = tid >> 5;
    int b = blockIdx.y;
    int n0 = blockIdx.x * 128;

    int mw = w >> 1;      // 0..3 -> m offset mw*32
    int nw = w & 1;       // 0..1 -> n offset nw*64

    wmma::fragment<wmma::accumulator, 16, 16, 8, float> acc[2][4];
#pragma unroll
    for (int i = 0; i < 2; i++)
#pragma unroll
        for (int j = 0; j < 4; j++)
            wmma::fill_fragment(acc[i][j], 0.f);

    // staging maps
    int arow = tid >> 1, ahalf = (tid & 1) * 16;       // A: 128 rows x 32
    int brow = tid >> 3, bn = (tid & 7) * 16;          // B: 32 rows x 128

    const float* xb0 = X0 + b * C_ * K_ + n0;
    const float* xb1 = (MODE == 0) ? X1 + b * C_ * K_ + n0 : nullptr;

    for (int c0 = 0; c0 < CIN; c0 += 32) {
        // ---- stage A: W[arow, c0+ahalf .. +16) -> As (tf32-rounded) ----
        {
            float* dst = As + arow * ALD + ahalf;
            if (arow < M) {
                const float* wp = W + arow * CIN + c0 + ahalf;
#pragma unroll
                for (int q = 0; q < 4; q++) {
                    float4 v = *reinterpret_cast<const float4*>(wp + q * 4);
                    dst[q * 4 + 0] = wmma::__float_to_tf32(v.x);
                    dst[q * 4 + 1] = wmma::__float_to_tf32(v.y);
                    dst[q * 4 + 2] = wmma::__float_to_tf32(v.z);
                    dst[q * 4 + 3] = wmma::__float_to_tf32(v.w);
                }
            } else {
#pragma unroll
                for (int q = 0; q < 16; q++) dst[q] = 0.f;
            }
        }
        // ---- stage B: X[c0+brow, n0+bn .. +16) -> Bs (BN/relu + tf32) ----
        {
            int cg = c0 + brow;
            const float* xp;
            if (MODE == 0)
                xp = (cg < C_) ? xb0 + cg * K_ : xb1 + (cg - C_) * K_;
            else
                xp = xb0 + cg * K_;
            float av = 0.f, dv = 0.f;
            if (MODE == 1) { av = __ldg(aa + cg); dv = __ldg(dd + cg); }
            float* dst = Bs + brow * BLD + bn;
#pragma unroll
            for (int q = 0; q < 4; q++) {
                float4 v = *reinterpret_cast<const float4*>(xp + bn + q * 4);
                if (MODE == 1) {
                    v.x = fmaxf(fmaf(v.x, av, dv), 0.f);
                    v.y = fmaxf(fmaf(v.y, av, dv), 0.f);
                    v.z = fmaxf(fmaf(v.z, av, dv), 0.f);
                    v.w = fmaxf(fmaf(v.w, av, dv), 0.f);
                }
                dst[q * 4 + 0] = wmma::__float_to_tf32(v.x);
                dst[q * 4 + 1] = wmma::__float_to_tf32(v.y);
                dst[q * 4 + 2] = wmma::__float_to_tf32(v.z);
                dst[q * 4 + 3] = wmma::__float_to_tf32(v.w);
            }
        }
        __syncthreads();

#pragma unroll
        for (int ks = 0; ks < 4; ks++) {
            wmma::fragment<wmma::matrix_a, 16, 16, 8, wmma::precision::tf32,
                           wmma::row_major> af[2];
            wmma::fragment<wmma::matrix_b, 16, 16, 8, wmma::precision::tf32,
                           wmma::row_major> bf[4];
#pragma unroll
            for (int i = 0; i < 2; i++)
                wmma::load_matrix_sync(af[i],
                    As + (mw * 32 + i * 16) * ALD + ks * 8, ALD);
#pragma unroll
            for (int j = 0; j < 4; j++)
                wmma::load_matrix_sync(bf[j],
                    Bs + ks * 8 * BLD + nw * 64 + j * 16, BLD);
#pragma unroll
            for (int i = 0; i < 2; i++)
#pragma unroll
                for (int j = 0; j < 4; j++)
                    wmma::mma_sync(acc[i][j], af[i], bf[j], acc[i][j]);
        }
        __syncthreads();
    }

    // ---- epilogue: two n-waves through smem; bias + stats + store ----
    int erow = tid >> 1;                 // 0..127
    int eoff = (tid & 1) * 32;
    float bb = (erow < M) ? __ldg(bias + erow) : 0.f;
    float s = 0.f, s2 = 0.f;

#pragma unroll
    for (int wave = 0; wave < 2; wave++) {
        if (nw == wave) {
#pragma unroll
            for (int i = 0; i < 2; i++)
#pragma unroll
                for (int j = 0; j < 4; j++)
                    wmma::store_matrix_sync(
                        Dsm + (mw * 32 + i * 16) * DLD + j * 16,
                        acc[i][j], DLD, wmma::mem_row_major);
        }
        __syncthreads();
        if (erow < M) {
            float* yp = Y + b * M * K_ + erow * K_ + n0 + wave * 64 + eoff;
            const float* sp = Dsm + erow * DLD + eoff;
#pragma unroll
            for (int q = 0; q < 8; q++) {
                float4 v = *reinterpret_cast<const float4*>(sp + q * 4);
                v.x += bb; v.y += bb; v.z += bb; v.w += bb;
                *reinterpret_cast<float4*>(yp + q * 4) = v;
                if (STATS) {
                    s += v.x + v.y + v.z + v.w;
                    s2 = fmaf(v.x, v.x, s2); s2 = fmaf(v.y, v.y, s2);
                    s2 = fmaf(v.z, v.z, s2); s2 = fmaf(v.w, v.w, s2);
                }
            }
        }
        __syncthreads();
    }

    if (STATS && erow < M) {
        s  += __shfl_xor_sync(0xffffffffu, s, 1);
        s2 += __shfl_xor_sync(0xffffffffu, s2, 1);
        if ((tid & 1) == 0) {
            atomicAdd(&sS[erow], s);
            atomicAdd(&sS2[erow], s2);
        }
    }
}

// ===========================================================================
// finalize BN fold: relu_bn(x) = relu(x*a + d)
// ===========================================================================
__global__ void finalize_kernel(const float* __restrict__ g,
                                const float* __restrict__ be,
                                const float* __restrict__ sS,
                                const float* __restrict__ sS2,
                                float* __restrict__ a, float* __restrict__ d) {
    int c = threadIdx.x;
    if (c < C_) {
        const float invN = 1.0f / (B_ * K_);
        float mean = sS[c] * invN;
        float var = sS2[c] * invN - mean * mean;
        float rstd = rsqrtf(var + 1e-5f);
        float av = rstd * g[c];
        a[c] = av;
        d[c] = be[c] - mean * av;
    }
}

// ===========================================================================
// Assemble the 183-channel output (SMEM transpose, coalesced both ways)
// ===========================================================================
__global__ void epilogue_kernel(const float* __restrict__ xyz,
                                const float* __restrict__ ms,
                                float* __restrict__ out) {
    __shared__ float s[OUTC * 65];
    __shared__ float sms[54];
    int tid = threadIdx.x;
    int k0 = blockIdx.x * 64;
    int b = blockIdx.y;

    if (tid < 54) sms[tid] = ms[tid];
    const float* tp = g_t + b * OUTC * K_ + k0;
    for (int e = tid; e < OUTC * 64; e += 256) {
        int o = e >> 6, k = e & 63;
        s[o * 65 + k] = tp[o * K_ + k];
    }
    __syncthreads();

    float* op = out + (b * K_ + k0) * OCH;
    for (int e = tid; e < 64 * OCH; e += 256) {
        int k = e / OCH;
        int ch = e - k * OCH;
        int o;
        float scale = 1.f, add = 0.f;
        if (ch < 27) {
            o = ch;
            if (ch < 3) add = xyz[(b * K_ + k0 + k) * 3 + ch];
        } else if (ch < 39) {
            o = ch - 12;
            scale = 0.26179938779914943f;
        } else if (ch < 111) {
            o = ch - 12;
        } else if (ch < 165) {
            o = ch - 66;
            scale = sms[ch - 111];
        } else {
            o = ch - 66;
        }
        op[e] = s[o * 65 + k] * scale + add;
    }
}

// ===========================================================================
extern "C" void kernel_launch(void* const* d_in, const int* in_sizes, int n_in,
                              void* d_out, int out_size) {
    (void)in_sizes; (void)n_in; (void)out_size;
    const float* xyz      = (const float*)d_in[0];
    const float* features = (const float*)d_in[1];
    const float* rn       = (const float*)d_in[2];
    const float* gt       = (const float*)d_in[3];
    const int*   pred     = (const int*)d_in[4];   // int32
    const float* W1 = (const float*)d_in[5];
    const float* b1 = (const float*)d_in[6];
    const float* g1 = (const float*)d_in[7];
    const float* be1 = (const float*)d_in[8];
    const float* W2 = (const float*)d_in[9];
    const float* b2 = (const float*)d_in[10];
    const float* g2 = (const float*)d_in[11];
    const float* be2 = (const float*)d_in[12];
    const float* W3 = (const float*)d_in[13];
    const float* b3 = (const float*)d_in[14];
    const float* ms = (const float*)d_in[15];
    float* out = (float*)d_out;

    const int OFF_IDX = B_ * K_ * OCH;
    const int OFF_SUM = OFF_IDX + B_ * K_;
    const int OFF_LBL = OFF_SUM + B_;

    float *p_net1, *p_net2, *p_t, *p_s, *p_s2, *p_a, *p_d;
    cudaGetSymbolAddress((void**)&p_net1, g_net1);
    cudaGetSymbolAddress((void**)&p_net2, g_net2);
    cudaGetSymbolAddress((void**)&p_t,    g_t);
    cudaGetSymbolAddress((void**)&p_s,    g_s);
    cudaGetSymbolAddress((void**)&p_s2,   g_s2);
    cudaGetSymbolAddress((void**)&p_a,    g_a);
    cudaGetSymbolAddress((void**)&p_d,    g_d);

    prep_kernel<<<B_, K_>>>(xyz, gt, pred,
                            out + OFF_LBL, out + OFF_IDX, out + OFF_SUM);

    dim3 gg(2, B_);
    wmma_gemm<256, 0, 1><<<gg, 256>>>(W1, b1, features, rn, nullptr, nullptr,
                                      p_net1, C_, p_s, p_s2);
    finalize_kernel<<<1, 128>>>(g1, be1, p_s, p_s2, p_a, p_d);
    wmma_gemm<128, 1, 1><<<gg, 256>>>(W2, b2, p_net1, nullptr, p_a, p_d,
                                      p_net2, C_, p_s + C_, p_s2 + C_);
    finalize_kernel<<<1, 128>>>(g2, be2, p_s + C_, p_s2 + C_, p_a + C_, p_d + C_);
    wmma_gemm<128, 1, 0><<<gg, 256>>>(W3, b3, p_net2, nullptr, p_a + C_, p_d + C_,
                                      p_t, OUTC, nullptr, nullptr);

    epilogue_kernel<<<dim3(K_ / 64, B_), 256>>>(xyz, ms, out);
}